// round 3
// baseline (speedup 1.0000x reference)
#include <cuda_runtime.h>
#include <math.h>

// EncoderSRNN: T=256 sequential steps, B=128 independent batch lanes.
// Design: G=2 batch lanes per CTA -> 64 independent CTAs, full recurrence
// inside ONE kernel (no inter-CTA communication). State in dynamic smem.
// Weights streamed from L2 each step with coalesced float4 LDG,
// lane-splits-K dot products + warp butterfly reductions.

#define T_STEPS 256
#define BATCH   128
#define HDIM    256
#define EDIM    256
#define SDIM    64
#define SSZ     64
#define G       2
#define NTHREADS 512
#define XPAD    656   // emb(256)+hid(256)+tops(128)=640, padded

struct SM {
    float x[G][XPAD];                 // [emb | hid | tops] per batch lane
    float stack[2][G][SSZ][SDIM];     // double-buffered stack
    float mh[G][HDIM];                // pre-activation mhid
    float pv[G][SDIM];                // push_val (post-relu)
    float uv[G][SDIM];                // u_val   (post-relu)
    float lg[G][4];                   // 3 act logits + gate
    float pr[G][4];                   // p_push, p_pop, p_noop
};

__device__ __forceinline__ float wred(float v) {
    v += __shfl_xor_sync(0xffffffffu, v, 16);
    v += __shfl_xor_sync(0xffffffffu, v, 8);
    v += __shfl_xor_sync(0xffffffffu, v, 4);
    v += __shfl_xor_sync(0xffffffffu, v, 2);
    v += __shfl_xor_sync(0xffffffffu, v, 1);
    return v;
}

__device__ __forceinline__ void dot4(float& acc, const float4 a, const float4 b) {
    acc = fmaf(a.x, b.x, fmaf(a.y, b.y, fmaf(a.z, b.z, fmaf(a.w, b.w, acc))));
}

__global__ void __launch_bounds__(NTHREADS, 1)
srnn_kernel(const int*   __restrict__ inputs,
            const float* __restrict__ emb_W,
            const float* __restrict__ W_hh, const float* __restrict__ b_hh,
            const float* __restrict__ W_eh, const float* __restrict__ b_eh,
            const float* __restrict__ W_ha, const float* __restrict__ b_ha,
            const float* __restrict__ W_hg, const float* __restrict__ b_hg,
            const float* __restrict__ W_hs, const float* __restrict__ b_hs,
            const float* __restrict__ W_sh, const float* __restrict__ b_sh,
            const float* __restrict__ W_su, const float* __restrict__ b_su,
            const float* __restrict__ empty_elem,
            float* __restrict__ out)
{
    extern __shared__ char smraw[];
    SM* sm = reinterpret_cast<SM*>(smraw);

    const int tid  = threadIdx.x;
    const int warp = tid >> 5;
    const int lane = tid & 31;

    float* out_outputs = out;                                   // [T,B,HDIM]
    float* out_hid     = out + (size_t)T_STEPS * BATCH * HDIM;  // [B,HDIM]
    float* out_stack   = out_hid + BATCH * HDIM;                // [B,SSZ,SDIM]
    float* out_acts    = out_stack + (size_t)BATCH * SSZ * SDIM;// [T,B]

    // ---- init: hid = 0, stack[0] = empty_elem broadcast ----
    {
        int b = tid >> 8, r = tid & 255;
        sm->x[b][256 + r] = 0.f;
    }
    for (int e = tid; e < G * SSZ * SDIM; e += NTHREADS) {
        ((float*)sm->stack[0])[e] = empty_elem[e & 63];
    }
    __syncthreads();

    int src = 0;

    const float4* x0 = reinterpret_cast<const float4*>(sm->x[0]);
    const float4* x1 = reinterpret_cast<const float4*>(sm->x[1]);

    for (int t = 0; t < T_STEPS; ++t) {
        // ---------- phase 1: load emb row + tops into x ----------
        {
            int b = tid >> 8, k = tid & 255;
            int bg = (blockIdx.x << 1) + b;
            int row = inputs[t * BATCH + bg];
            sm->x[b][k] = emb_W[(size_t)row * EDIM + k];
        }
        if (tid < G * 2 * SDIM) {   // tops = stack rows 0,1
            int b = tid >> 7, kk = tid & 127;
            sm->x[b][512 + kk] = sm->stack[src][b][kk >> 6][kk & 63];
        }
        __syncthreads();

        // ---------- phase 2: all mat-vecs (old state) ----------
        // mhid: 256 rows over K=640
        #pragma unroll 2
        for (int j = 0; j < 16; ++j) {
            int r = (j << 4) + warp;
            const float4* We = reinterpret_cast<const float4*>(W_eh) + r * 64;
            const float4* Wh = reinterpret_cast<const float4*>(W_hh) + r * 64;
            const float4* Ws = reinterpret_cast<const float4*>(W_sh) + r * 32;
            float4 w0 = We[lane], w1 = We[lane + 32];
            float4 w2 = Wh[lane], w3 = Wh[lane + 32];
            float4 w4 = Ws[lane];
            float a0 = 0.f, a1 = 0.f;
            float4 v;
            v = x0[lane];        dot4(a0, w0, v);
            v = x0[lane + 32];   dot4(a0, w1, v);
            v = x0[64 + lane];   dot4(a0, w2, v);
            v = x0[96 + lane];   dot4(a0, w3, v);
            v = x0[128 + lane];  dot4(a0, w4, v);
            v = x1[lane];        dot4(a1, w0, v);
            v = x1[lane + 32];   dot4(a1, w1, v);
            v = x1[64 + lane];   dot4(a1, w2, v);
            v = x1[96 + lane];   dot4(a1, w3, v);
            v = x1[128 + lane];  dot4(a1, w4, v);
            a0 = wred(a0); a1 = wred(a1);
            if (lane == 0) {
                float bias = b_eh[r] + b_hh[r] + b_sh[r];
                sm->mh[0][r] = a0 + bias;
                sm->mh[1][r] = a1 + bias;
            }
        }
        // push_val: 64 rows over hid (K=256)
        #pragma unroll 2
        for (int j = 0; j < 4; ++j) {
            int r = (j << 4) + warp;
            const float4* W = reinterpret_cast<const float4*>(W_hs) + r * 64;
            float4 w0 = W[lane], w1 = W[lane + 32];
            float a0 = 0.f, a1 = 0.f;
            float4 v;
            v = x0[64 + lane]; dot4(a0, w0, v);
            v = x0[96 + lane]; dot4(a0, w1, v);
            v = x1[64 + lane]; dot4(a1, w0, v);
            v = x1[96 + lane]; dot4(a1, w1, v);
            a0 = wred(a0); a1 = wred(a1);
            if (lane == 0) {
                float bb = b_hs[r];
                sm->pv[0][r] = fmaxf(a0 + bb, 0.f);
                sm->pv[1][r] = fmaxf(a1 + bb, 0.f);
            }
        }
        // u_val: 64 rows over tops (K=128)
        #pragma unroll 2
        for (int j = 0; j < 4; ++j) {
            int r = (j << 4) + warp;
            const float4* W = reinterpret_cast<const float4*>(W_su) + r * 32;
            float4 w0 = W[lane];
            float a0 = 0.f, a1 = 0.f;
            float4 v;
            v = x0[128 + lane]; dot4(a0, w0, v);
            v = x1[128 + lane]; dot4(a1, w0, v);
            a0 = wred(a0); a1 = wred(a1);
            if (lane == 0) {
                float bb = b_su[r];
                sm->uv[0][r] = fmaxf(a0 + bb, 0.f);
                sm->uv[1][r] = fmaxf(a1 + bb, 0.f);
            }
        }
        // act logits (3 rows) + gate (1 row) over hid
        if (warp < 4) {
            const float* Wrow = (warp < 3) ? (W_ha + warp * 256) : W_hg;
            const float4* W = reinterpret_cast<const float4*>(Wrow);
            float4 w0 = W[lane], w1 = W[lane + 32];
            float a0 = 0.f, a1 = 0.f;
            float4 v;
            v = x0[64 + lane]; dot4(a0, w0, v);
            v = x0[96 + lane]; dot4(a0, w1, v);
            v = x1[64 + lane]; dot4(a1, w0, v);
            v = x1[96 + lane]; dot4(a1, w1, v);
            a0 = wred(a0); a1 = wred(a1);
            if (lane == 0) {
                float bb = (warp < 3) ? b_ha[warp] : b_hg[0];
                sm->lg[0][warp] = a0 + bb;
                sm->lg[1][warp] = a1 + bb;
            }
        }
        __syncthreads();

        // ---------- phase 3: probs, argmax ----------
        if (tid < G) {
            int b = tid;
            float l0 = sm->lg[b][0], l1 = sm->lg[b][1], l2 = sm->lg[b][2];
            float g  = sm->lg[b][3];
            float sp = (g > 20.f) ? g : log1pf(expf(g));
            float gamma = 1.f + sp;
            float m = fmaxf(l0, fmaxf(l1, l2));
            float e0 = expf(l0 - m), e1 = expf(l1 - m), e2 = expf(l2 - m);
            float ls = logf(e0 + e1 + e2);
            float s0 = expf(gamma * ((l0 - m) - ls));
            float s1 = expf(gamma * ((l1 - m) - ls));
            float s2 = expf(gamma * ((l2 - m) - ls));
            float inv = 1.f / (s0 + s1 + s2 + 1e-16f);
            sm->pr[b][0] = s0 * inv;
            sm->pr[b][1] = s1 * inv;
            sm->pr[b][2] = s2 * inv;
            int idx = 0; float best = s0;
            if (s1 > best) { best = s1; idx = 1; }
            if (s2 > best) idx = 2;
            int bg = (blockIdx.x << 1) + b;
            out_acts[t * BATCH + bg] = (float)idx;
        }
        __syncthreads();

        // ---------- phase 4: new hid + outputs + stack update ----------
        {
            int b = tid >> 8, r = tid & 255;
            float h = fmaxf(sm->mh[b][r], 0.f);
            sm->x[b][256 + r] = h;
            int bg = (blockIdx.x << 1) + b;
            out_outputs[((size_t)t * BATCH + bg) * HDIM + r] = h;
        }
        int dst = src ^ 1;
        #pragma unroll
        for (int j = 0; j < 16; ++j) {
            int e = tid + (j << 9);
            int b = e >> 12, rem = e & 4095;
            int i = rem >> 6, d = rem & 63;
            float pp = sm->pr[b][0], pq = sm->pr[b][1], pn = sm->pr[b][2];
            const float (*S)[SDIM] = sm->stack[src][b];
            float cur = S[i][d];
            float pushsrc = (i == 0) ? sm->pv[b][d] : S[i - 1][d];
            float popsrc  = (i == 0) ? sm->uv[b][d]
                                     : ((i < SSZ - 1) ? S[i + 1][d] : 0.f);
            sm->stack[dst][b][i][d] = pp * pushsrc + pq * popsrc + pn * cur;
        }
        __syncthreads();
        src = dst;
    }

    // ---------- final state outputs ----------
    {
        int b = tid >> 8, r = tid & 255;
        int bg = (blockIdx.x << 1) + b;
        out_hid[bg * HDIM + r] = sm->x[b][256 + r];
    }
    #pragma unroll
    for (int j = 0; j < 16; ++j) {
        int e = tid + (j << 9);
        int b = e >> 12, rem = e & 4095;
        int bg = (blockIdx.x << 1) + b;
        out_stack[(size_t)bg * SSZ * SDIM + rem] = ((float*)sm->stack[src][b])[rem];
    }
}

extern "C" void kernel_launch(void* const* d_in, const int* in_sizes, int n_in,
                              void* d_out, int out_size) {
    cudaFuncSetAttribute(srnn_kernel,
                         cudaFuncAttributeMaxDynamicSharedMemorySize,
                         (int)sizeof(SM));
    srnn_kernel<<<BATCH / G, NTHREADS, sizeof(SM)>>>(
        (const int*)  d_in[0],   // inputs
        (const float*)d_in[1],   // emb_W
        (const float*)d_in[2],   // W_hh
        (const float*)d_in[3],   // b_hh
        (const float*)d_in[4],   // W_eh
        (const float*)d_in[5],   // b_eh
        (const float*)d_in[6],   // W_ha
        (const float*)d_in[7],   // b_ha
        (const float*)d_in[8],   // W_hg
        (const float*)d_in[9],   // b_hg
        (const float*)d_in[10],  // W_hs
        (const float*)d_in[11],  // b_hs
        (const float*)d_in[12],  // W_sh
        (const float*)d_in[13],  // b_sh
        (const float*)d_in[14],  // W_su
        (const float*)d_in[15],  // b_su
        (const float*)d_in[16],  // empty_elem
        (float*)d_out);
}

// round 4
// speedup vs baseline: 1.6501x; 1.6501x over previous
#include <cuda_runtime.h>
#include <math.h>
#include <stdint.h>

// EncoderSRNN on GB300: 4-CTA cluster, weights SMEM-resident (row-split),
// f32x2 packed FMAs over batch-lane pairs, DSMEM state exchange.
// 32 clusters x 4 CTAs = 128 CTAs; cluster serves 4 batch lanes (lane = rank).

#define T_STEPS 256
#define BATCH   128
#define HDIM    256
#define SDIM    64
#define SSZ     64
#define NT      512
#define KTOT    640          // emb 256 | hid 256 | tops 128
#define WPAD    641          // 641 mod 32 == 1 -> conflict-free
#define XPITCH  648          // float2 elements per pair-row

typedef unsigned long long ull;

struct SM {
    float  Wm[64][WPAD];      // fused [W_eh|W_hh|W_sh] rows 64*rank..+64   164096 B
    float  Whs[16][256];      // W_hs rows 16*rank..+16                      16384 B
    float  Wsu[16][128];      //                                              8192 B
    float  Whd[4][256];       // W_ha rows 0-2, W_hg row 3 (replicated)       4096 B
    float2 xpk[2][XPITCH];    // x packed by lane-pairs: [pair][k]={x[2p],x[2p+1]} 10368 B
    float  hidrx[4][256];     // received new hid (all 256 rows, 4 lanes)     4096 B
    float  stck[SSZ][SDIM];   // own lane's stack                            16384 B
    float  pvbuf[64];
    float  uvbuf[64];
    float  biasm[64];
    float  bhs[16];
    float  bsu[16];
    float  bhd[4];
    float  lg[4];             // act logits 0-2, gate 3 (own lane)
    float  pr[4];             // p_push, p_pop, p_noop
};                            // ~224.6 KB total

// float index into xpk for (batch lane b, k)
#define XI(b,k) (((b) >> 1) * (2 * XPITCH) + 2 * (k) + ((b) & 1))

__device__ __forceinline__ uint32_t s32(const void* p) {
    return (uint32_t)__cvta_generic_to_shared(p);
}
__device__ __forceinline__ void stc(uint32_t laddr, uint32_t rank, float v) {
    uint32_t ra;
    asm volatile("mapa.shared::cluster.u32 %0, %1, %2;" : "=r"(ra) : "r"(laddr), "r"(rank));
    asm volatile("st.shared::cluster.f32 [%0], %1;" :: "r"(ra), "f"(v) : "memory");
}
__device__ __forceinline__ void cluster_sync() {
    asm volatile("barrier.cluster.arrive.aligned;" ::: "memory");
    asm volatile("barrier.cluster.wait.aligned;" ::: "memory");
}
__device__ __forceinline__ uint32_t ctarank() {
    uint32_t r; asm("mov.u32 %0, %%cluster_ctarank;" : "=r"(r)); return r;
}
__device__ __forceinline__ ull ffma2(ull a, ull b, ull c) {
    ull d; asm("fma.rn.f32x2 %0, %1, %2, %3;" : "=l"(d) : "l"(a), "l"(b), "l"(c)); return d;
}
__device__ __forceinline__ ull fadd2(ull a, ull b) {
    ull d; asm("add.rn.f32x2 %0, %1, %2;" : "=l"(d) : "l"(a), "l"(b)); return d;
}
__device__ __forceinline__ ull bcast2(float f) {
    ull d; asm("mov.b64 %0, {%1, %1};" : "=l"(d) : "f"(f)); return d;
}
__device__ __forceinline__ float2 unpk(ull v) {
    float2 u; asm("mov.b64 {%0, %1}, %2;" : "=f"(u.x), "=f"(u.y) : "l"(v)); return u;
}
__device__ __forceinline__ ull wred2(ull v) {
    #pragma unroll
    for (int o = 16; o >= 1; o >>= 1)
        v = fadd2(v, __shfl_xor_sync(0xffffffffu, v, o));
    return v;
}
__device__ __forceinline__ float wred1(float v) {
    #pragma unroll
    for (int o = 16; o >= 1; o >>= 1)
        v += __shfl_xor_sync(0xffffffffu, v, o);
    return v;
}

__global__ void __launch_bounds__(NT, 1) __cluster_dims__(4, 1, 1)
srnn_kernel(const int*   __restrict__ inputs,
            const float* __restrict__ emb_W,
            const float* __restrict__ W_hh, const float* __restrict__ b_hh,
            const float* __restrict__ W_eh, const float* __restrict__ b_eh,
            const float* __restrict__ W_ha, const float* __restrict__ b_ha,
            const float* __restrict__ W_hg, const float* __restrict__ b_hg,
            const float* __restrict__ W_hs, const float* __restrict__ b_hs,
            const float* __restrict__ W_sh, const float* __restrict__ b_sh,
            const float* __restrict__ W_su, const float* __restrict__ b_su,
            const float* __restrict__ empty_elem,
            float* __restrict__ out)
{
    extern __shared__ char raw[];
    SM* sm = reinterpret_cast<SM*>(raw);

    const int tid  = threadIdx.x;
    const int warp = tid >> 5;
    const int lane = tid & 31;
    const uint32_t rank = ctarank();
    const int clus = blockIdx.x >> 2;

    float* out_outputs = out;
    float* out_hid     = out + (size_t)T_STEPS * BATCH * HDIM;
    float* out_stack   = out_hid + BATCH * HDIM;
    float* out_acts    = out_stack + (size_t)BATCH * SSZ * SDIM;

    const uint32_t hidrx_a = s32(&sm->hidrx[0][0]);
    const uint32_t pv_a    = s32(&sm->pvbuf[0]);
    const uint32_t uv_a    = s32(&sm->uvbuf[0]);
    const uint32_t xpk_a   = s32(&sm->xpk[0][0]);

    // ================= init: load resident weights & state =================
    for (int idx = tid; idx < 64 * KTOT; idx += NT) {
        int r = idx / KTOT, k = idx - r * KTOT;
        int R = 64 * rank + r;
        float v;
        if (k < 256)      v = W_eh[R * 256 + k];
        else if (k < 512) v = W_hh[R * 256 + (k - 256)];
        else              v = W_sh[R * 128 + (k - 512)];
        sm->Wm[r][k] = v;
    }
    for (int idx = tid; idx < 16 * 256; idx += NT) {
        int r = idx >> 8, k = idx & 255;
        sm->Whs[r][k] = W_hs[(16 * rank + r) * 256 + k];
    }
    for (int idx = tid; idx < 16 * 128; idx += NT) {
        int r = idx >> 7, k = idx & 127;
        sm->Wsu[r][k] = W_su[(16 * rank + r) * 128 + k];
    }
    for (int idx = tid; idx < 4 * 256; idx += NT) {
        int r = idx >> 8, k = idx & 255;
        sm->Whd[r][k] = (r < 3) ? W_ha[r * 256 + k] : W_hg[k];
    }
    if (tid < 64) {
        int R = 64 * rank + tid;
        sm->biasm[tid] = b_eh[R] + b_hh[R] + b_sh[R];
        if (tid < 16) {
            sm->bhs[tid] = b_hs[16 * rank + tid];
            sm->bsu[tid] = b_su[16 * rank + tid];
        }
        if (tid < 4) sm->bhd[tid] = (tid < 3) ? b_ha[tid] : b_hg[0];
    }
    for (int e = tid; e < SSZ * SDIM; e += NT)
        sm->stck[e >> 6][e & 63] = empty_elem[e & 63];
    // x: hid=0, tops=empty_elem, emb for t=0
    for (int e = tid; e < 4 * (KTOT - 256); e += NT) {   // k in [256,640)
        int b = e >> 8 & 0 ; // placeholder (unused)
        (void)b;
        int bb = e / (KTOT - 256);
        int k  = 256 + (e - bb * (KTOT - 256));
        float v = (k < 512) ? 0.f : empty_elem[(k - 512) & 63];
        ((float*)sm->xpk)[XI(bb, k)] = v;
    }
    {
        int b = tid >> 7, k = tid & 127;
        int bg = clus * 4 + b;
        int row = inputs[bg];
        ((float*)sm->xpk)[XI(b, k)]       = emb_W[(size_t)row * 256 + k];
        ((float*)sm->xpk)[XI(b, k + 128)] = emb_W[(size_t)row * 256 + k + 128];
    }
    cluster_sync();

    const ull* xq = reinterpret_cast<const ull*>(sm->xpk);  // xq[p*XPITCH + k]

    // ============================ time loop ============================
    for (int t = 0; t < T_STEPS; ++t) {
        // ---- phase A ----
        // emb prefetch for t+1 (held in regs, stored in phase B)
        float pe0, pe1;
        {
            int tn = (t + 1 < T_STEPS) ? t + 1 : T_STEPS - 1;
            int b = tid >> 7, k = tid & 127;
            int row = inputs[tn * BATCH + clus * 4 + b];
            pe0 = emb_W[(size_t)row * 256 + k];
            pe1 = emb_W[(size_t)row * 256 + k + 128];
        }

        // mhid: warp w owns local rows {w, w+16, w+32, w+48}, k = lane + 32j
        {
            ull acc[4][2];
            #pragma unroll
            for (int r4 = 0; r4 < 4; ++r4) { acc[r4][0] = 0ull; acc[r4][1] = 0ull; }
            const float* wpl = &sm->Wm[warp][lane];
            #pragma unroll 4
            for (int j = 0; j < 20; ++j) {
                int k = lane + 32 * j;
                ull xa = xq[k];
                ull xb = xq[XPITCH + k];
                #pragma unroll
                for (int r4 = 0; r4 < 4; ++r4) {
                    ull w2 = bcast2(wpl[r4 * (16 * WPAD) + 32 * j]);
                    acc[r4][0] = ffma2(w2, xa, acc[r4][0]);
                    acc[r4][1] = ffma2(w2, xb, acc[r4][1]);
                }
            }
            #pragma unroll
            for (int r4 = 0; r4 < 4; ++r4) {
                acc[r4][0] = wred2(acc[r4][0]);
                acc[r4][1] = wred2(acc[r4][1]);
            }
            if (lane < 16) {
                int r4 = lane >> 2, b = lane & 3;
                float2 u = unpk(acc[r4][(b >> 1)]);
                float val = (b & 1) ? u.y : u.x;
                int rloc = warp + 16 * r4;
                int R = 64 * rank + rloc;
                float h = fmaxf(val + sm->biasm[rloc], 0.f);
                out_outputs[((size_t)t * BATCH + clus * 4 + b) * HDIM + R] = h;
                uint32_t off = hidrx_a + (uint32_t)(b * 256 + R) * 4u;
                #pragma unroll
                for (int p = 0; p < 4; ++p) stc(off, p, h);
            }
        }

        // pv: warp w -> row 16*rank + w over hid
        {
            ull a0 = 0ull, a1 = 0ull;
            #pragma unroll
            for (int j = 0; j < 8; ++j) {
                int k = lane + 32 * j;
                ull w2 = bcast2(sm->Whs[warp][k]);
                a0 = ffma2(w2, xq[256 + k], a0);
                a1 = ffma2(w2, xq[XPITCH + 256 + k], a1);
            }
            a0 = wred2(a0); a1 = wred2(a1);
            if (lane < 4) {
                float2 u0 = unpk(a0), u1 = unpk(a1);
                float v = (lane == 0) ? u0.x : (lane == 1) ? u0.y : (lane == 2) ? u1.x : u1.y;
                v = fmaxf(v + sm->bhs[warp], 0.f);
                stc(pv_a + (uint32_t)(16 * rank + warp) * 4u, (uint32_t)lane, v);
            }
        }
        // uv: warp w -> row 16*rank + w over tops
        {
            ull a0 = 0ull, a1 = 0ull;
            #pragma unroll
            for (int j = 0; j < 4; ++j) {
                int k = lane + 32 * j;
                ull w2 = bcast2(sm->Wsu[warp][k]);
                a0 = ffma2(w2, xq[512 + k], a0);
                a1 = ffma2(w2, xq[XPITCH + 512 + k], a1);
            }
            a0 = wred2(a0); a1 = wred2(a1);
            if (lane < 4) {
                float2 u0 = unpk(a0), u1 = unpk(a1);
                float v = (lane == 0) ? u0.x : (lane == 1) ? u0.y : (lane == 2) ? u1.x : u1.y;
                v = fmaxf(v + sm->bsu[warp], 0.f);
                stc(uv_a + (uint32_t)(16 * rank + warp) * 4u, (uint32_t)lane, v);
            }
        }
        // heads (own lane only): warps 0-3
        if (warp < 4) {
            const float* xf = (const float*)sm->xpk;
            float a = 0.f;
            #pragma unroll
            for (int j = 0; j < 8; ++j) {
                int k = lane + 32 * j;
                a = fmaf(sm->Whd[warp][k], xf[XI((int)rank, 256 + k)], a);
            }
            a = wred1(a);
            if (lane == 0) sm->lg[warp] = a + sm->bhd[warp];
        }

        cluster_sync();   // sync 1: partials delivered, local x reads done

        // ---- phase B ----
        if (tid == 0) {
            float l0 = sm->lg[0], l1 = sm->lg[1], l2 = sm->lg[2], g = sm->lg[3];
            float sp = (g > 20.f) ? g : log1pf(expf(g));
            float gamma = 1.f + sp;
            float m = fmaxf(l0, fmaxf(l1, l2));
            float e0 = expf(l0 - m), e1 = expf(l1 - m), e2 = expf(l2 - m);
            float ls = logf(e0 + e1 + e2);
            float s0 = expf(gamma * ((l0 - m) - ls));
            float s1 = expf(gamma * ((l1 - m) - ls));
            float s2 = expf(gamma * ((l2 - m) - ls));
            float inv = 1.f / (s0 + s1 + s2 + 1e-16f);
            sm->pr[0] = s0 * inv; sm->pr[1] = s1 * inv; sm->pr[2] = s2 * inv;
            int idx = 0; float best = s0;
            if (s1 > best) { best = s1; idx = 1; }
            if (s2 > best) idx = 2;
            out_acts[t * BATCH + clus * 4 + rank] = (float)idx;
        }
        // copy received hid into x, store prefetched emb
        {
            float* xf = (float*)sm->xpk;
            #pragma unroll
            for (int j = 0; j < 2; ++j) {
                int e = tid + j * NT;
                int b = e >> 8, k = e & 255;
                xf[XI(b, 256 + k)] = sm->hidrx[b][k];
            }
            int b = tid >> 7, k = tid & 127;
            xf[XI(b, k)]       = pe0;
            xf[XI(b, k + 128)] = pe1;
        }
        // stack update (register-staged, single buffer)
        float cur[8], ps[8], qs[8];
        #pragma unroll
        for (int j = 0; j < 8; ++j) {
            int e = tid + j * NT;
            int i = e >> 6, d = e & 63;
            cur[j] = sm->stck[i][d];
            ps[j]  = (i == 0) ? sm->pvbuf[d] : sm->stck[i - 1][d];
            qs[j]  = (i == 0) ? sm->uvbuf[d]
                              : ((i < SSZ - 1) ? sm->stck[i + 1][d] : 0.f);
        }
        __syncthreads();
        {
            float pp = sm->pr[0], pq = sm->pr[1], pn = sm->pr[2];
            #pragma unroll
            for (int j = 0; j < 8; ++j) {
                int e = tid + j * NT;
                int i = e >> 6, d = e & 63;
                float nv = pp * ps[j] + pq * qs[j] + pn * cur[j];
                sm->stck[i][d] = nv;
                if (i < 2) {   // new tops -> broadcast into everyone's x
                    int kx = 512 + i * 64 + d;
                    uint32_t off = xpk_a + (uint32_t)XI((int)rank, kx) * 4u;
                    #pragma unroll
                    for (int p = 0; p < 4; ++p) stc(off, p, nv);
                }
            }
        }
        cluster_sync();   // sync 2: x fully assembled for next step
    }

    // ================= final state outputs =================
    {
        int bg = clus * 4 + rank;
        if (tid < 256) out_hid[bg * HDIM + tid] = sm->hidrx[rank][tid];
        for (int e = tid; e < SSZ * SDIM; e += NT)
            out_stack[(size_t)bg * SSZ * SDIM + e] = sm->stck[e >> 6][e & 63];
    }
}

extern "C" void kernel_launch(void* const* d_in, const int* in_sizes, int n_in,
                              void* d_out, int out_size) {
    cudaFuncSetAttribute(srnn_kernel,
                         cudaFuncAttributeMaxDynamicSharedMemorySize,
                         (int)sizeof(SM));
    srnn_kernel<<<BATCH, NT, sizeof(SM)>>>(
        (const int*)  d_in[0],
        (const float*)d_in[1],
        (const float*)d_in[2],  (const float*)d_in[3],
        (const float*)d_in[4],  (const float*)d_in[5],
        (const float*)d_in[6],  (const float*)d_in[7],
        (const float*)d_in[8],  (const float*)d_in[9],
        (const float*)d_in[10], (const float*)d_in[11],
        (const float*)d_in[12], (const float*)d_in[13],
        (const float*)d_in[14], (const float*)d_in[15],
        (const float*)d_in[16],
        (float*)d_out);
}

// round 5
// speedup vs baseline: 2.2160x; 1.3429x over previous
#include <cuda_runtime.h>
#include <math.h>
#include <stdint.h>

// EncoderSRNN GB300 R5: 4-CTA cluster, mhid weights REGISTER-resident,
// x broadcast via LDS.128, one cluster_sync per step, all-local phase B.

#define T_STEPS 256
#define BATCH   128
#define HDIM    256
#define SDIM    64
#define SSZ     64
#define NT      512
#define KTOT    640
#define XQP     656     // ull pitch per batch-pair in xq
#define NKW     40      // k per warp slice (16 warps * 40 = 640)

typedef unsigned long long ull;

struct SM {
    float4 x4[KTOT];            // x[k] = {b0,b1,b2,b3}          10240 B
    float4 tc4[128];            // old-tops copy (k 512..639)     2048 B
    float4 part4[16 * 64];      // mhid partials [w][row]        16384 B
    float  stck[2][SSZ][SDIM];  // own-lane stack, dbl-buf       32768 B
    ull    xq[2][XQP];          // pair layout for pv/uv/heads   10496 B
    float  hidrx[2][4][HDIM];   // dbl-buf received hid           8192 B
    float  pvb[2][4][SDIM];     //                                2048 B
    float  uvb[2][4][SDIM];     //                                2048 B
    float  s2b[2][4][SDIM];     // old stack row2, all lanes      2048 B
    float  Whs[16][256];        // pv weights (own 16 rows)      16384 B
    float  Wsu[16][128];        //                                8192 B
    float  Whd[4][256];         // head rows 0-2=W_ha, 3=W_hg     4096 B
    float  biasm[64];
    float  bhs[16], bsu[16], bhd[4];
    float  lg[4][4];            // [b][head row]
    float  pr[4][4];            // [b][push,pop,noop]
};

__device__ __forceinline__ uint32_t s32(const void* p) {
    return (uint32_t)__cvta_generic_to_shared(p);
}
__device__ __forceinline__ uint32_t mapa_r(uint32_t a, uint32_t r) {
    uint32_t ra;
    asm("mapa.shared::cluster.u32 %0, %1, %2;" : "=r"(ra) : "r"(a), "r"(r));
    return ra;
}
__device__ __forceinline__ void stcf(uint32_t addr, float v) {
    asm volatile("st.shared::cluster.f32 [%0], %1;" :: "r"(addr), "f"(v) : "memory");
}
__device__ __forceinline__ void cluster_sync() {
    asm volatile("barrier.cluster.arrive.aligned;" ::: "memory");
    asm volatile("barrier.cluster.wait.aligned;" ::: "memory");
}
__device__ __forceinline__ uint32_t ctarank() {
    uint32_t r; asm("mov.u32 %0, %%cluster_ctarank;" : "=r"(r)); return r;
}
__device__ __forceinline__ ull ffma2(ull a, ull b, ull c) {
    ull d; asm("fma.rn.f32x2 %0, %1, %2, %3;" : "=l"(d) : "l"(a), "l"(b), "l"(c)); return d;
}
__device__ __forceinline__ ull fadd2(ull a, ull b) {
    ull d; asm("add.rn.f32x2 %0, %1, %2;" : "=l"(d) : "l"(a), "l"(b)); return d;
}
__device__ __forceinline__ ull bcast2(float f) {
    ull d; asm("mov.b64 %0, {%1, %1};" : "=l"(d) : "f"(f)); return d;
}
__device__ __forceinline__ float2 unpk(ull v) {
    float2 u; asm("mov.b64 {%0, %1}, %2;" : "=f"(u.x), "=f"(u.y) : "l"(v)); return u;
}
__device__ __forceinline__ ull wred2(ull v) {
    #pragma unroll
    for (int o = 16; o >= 1; o >>= 1)
        v = fadd2(v, __shfl_xor_sync(0xffffffffu, v, o));
    return v;
}
__device__ __forceinline__ float pick4(int lane, ull a0, ull a1) {
    float2 u0 = unpk(a0), u1 = unpk(a1);
    return (lane == 0) ? u0.x : (lane == 1) ? u0.y : (lane == 2) ? u1.x : u1.y;
}
__device__ __forceinline__ float loadW(const float* We, const float* Wh,
                                       const float* Ws, int R, int k) {
    if (k < 256) return We[R * 256 + k];
    if (k < 512) return Wh[R * 256 + (k - 256)];
    return Ws[R * 128 + (k - 512)];
}

__global__ void __launch_bounds__(NT, 1) __cluster_dims__(4, 1, 1)
srnn_kernel(const int*   __restrict__ inputs,
            const float* __restrict__ emb_W,
            const float* __restrict__ W_hh, const float* __restrict__ b_hh,
            const float* __restrict__ W_eh, const float* __restrict__ b_eh,
            const float* __restrict__ W_ha, const float* __restrict__ b_ha,
            const float* __restrict__ W_hg, const float* __restrict__ b_hg,
            const float* __restrict__ W_hs, const float* __restrict__ b_hs,
            const float* __restrict__ W_sh, const float* __restrict__ b_sh,
            const float* __restrict__ W_su, const float* __restrict__ b_su,
            const float* __restrict__ empty_elem,
            float* __restrict__ out)
{
    extern __shared__ char raw[];
    SM* sm = reinterpret_cast<SM*>(raw);

    const int tid  = threadIdx.x;
    const int warp = tid >> 5;
    const int lane = tid & 31;
    const uint32_t rank = ctarank();
    const int clus = blockIdx.x >> 2;

    float* out_outputs = out;
    float* out_hid     = out + (size_t)T_STEPS * BATCH * HDIM;
    float* out_stack   = out_hid + BATCH * HDIM;
    float* out_acts    = out_stack + (size_t)BATCH * SSZ * SDIM;

    float* x4f = (float*)sm->x4;
    float* xqf = (float*)sm->xq;
    float* tcf = (float*)sm->tc4;

    // hoisted remote bases (DSMEM windows of all 4 cluster CTAs)
    uint32_t r_hid[4], r_pv[4], r_uv[4], r_s2[4];
    #pragma unroll
    for (int d = 0; d < 4; ++d) {
        r_hid[d] = mapa_r(s32(&sm->hidrx[0][0][0]), d);
        r_pv[d]  = mapa_r(s32(&sm->pvb[0][0][0]),   d);
        r_uv[d]  = mapa_r(s32(&sm->uvb[0][0][0]),   d);
        r_s2[d]  = mapa_r(s32(&sm->s2b[0][0][0]),   d);
    }

    // ===================== init =====================
    float wr0[NKW], wr1[NKW];
    {
        int R0 = 64 * (int)rank + lane, R1 = R0 + 32;
        int kb = NKW * warp;
        #pragma unroll
        for (int i = 0; i < NKW; ++i) {
            wr0[i] = loadW(W_eh, W_hh, W_sh, R0, kb + i);
            wr1[i] = loadW(W_eh, W_hh, W_sh, R1, kb + i);
        }
    }
    for (int idx = tid; idx < 16 * 256; idx += NT) {
        int r = idx >> 8, k = idx & 255;
        sm->Whs[r][k] = W_hs[(16 * rank + r) * 256 + k];
    }
    for (int idx = tid; idx < 16 * 128; idx += NT) {
        int r = idx >> 7, k = idx & 127;
        sm->Wsu[r][k] = W_su[(16 * rank + r) * 128 + k];
    }
    for (int idx = tid; idx < 4 * 256; idx += NT) {
        int r = idx >> 8, k = idx & 255;
        sm->Whd[r][k] = (r < 3) ? W_ha[r * 256 + k] : W_hg[k];
    }
    if (tid < 64) {
        int R = 64 * rank + tid;
        sm->biasm[tid] = b_eh[R] + b_hh[R] + b_sh[R];
        if (tid < 16) {
            sm->bhs[tid] = b_hs[16 * rank + tid];
            sm->bsu[tid] = b_su[16 * rank + tid];
        }
        if (tid < 4) sm->bhd[tid] = (tid < 3) ? b_ha[tid] : b_hg[0];
    }
    // x init: emb(t=0) | hid=0 | tops=empty ; mirror into xq
    for (int e = tid; e < KTOT * 4; e += NT) {
        int k = e >> 2, b = e & 3;
        float v;
        if (k < 256) {
            int row = inputs[clus * 4 + b];
            v = emb_W[(size_t)row * 256 + k];
        } else if (k < 512) v = 0.f;
        else                v = empty_elem[(k - 512) & 63];
        x4f[k * 4 + b] = v;
        xqf[((b >> 1) * XQP + k) * 2 + (b & 1)] = v;
    }
    for (int e = tid; e < SSZ * SDIM; e += NT)
        sm->stck[0][e >> 6][e & 63] = empty_elem[e & 63];
    cluster_sync();

    // ===================== time loop =====================
    for (int t = 0; t < T_STEPS; ++t) {
        const int p  = t & 1;          // exchange-buffer parity
        const int sp = t & 1;          // stack src parity

        // ---- A1: emb prefetch (regs), tops copy, mhid partials ----
        float pe0, pe1;
        {
            int tn = (t + 1 < T_STEPS) ? t + 1 : T_STEPS - 1;
            int b = tid >> 7, k = tid & 127;
            int row = inputs[tn * BATCH + clus * 4 + b];
            pe0 = emb_W[(size_t)row * 256 + k];
            pe1 = emb_W[(size_t)row * 256 + k + 128];
        }
        if (tid < 128) sm->tc4[tid] = sm->x4[512 + tid];

        {
            ull a00 = 0, a01 = 0, a10 = 0, a11 = 0;
            const ulonglong2* xv =
                reinterpret_cast<const ulonglong2*>(sm->x4) + NKW * warp;
            #pragma unroll
            for (int i = 0; i < NKW; ++i) {
                ulonglong2 xx = xv[i];
                ull w0 = bcast2(wr0[i]);
                a00 = ffma2(w0, xx.x, a00);
                a01 = ffma2(w0, xx.y, a01);
                ull w1 = bcast2(wr1[i]);
                a10 = ffma2(w1, xx.x, a10);
                a11 = ffma2(w1, xx.y, a11);
            }
            float2 u0 = unpk(a00), u1 = unpk(a01);
            sm->part4[warp * 64 + lane]      = make_float4(u0.x, u0.y, u1.x, u1.y);
            float2 v0 = unpk(a10), v1 = unpk(a11);
            sm->part4[warp * 64 + lane + 32] = make_float4(v0.x, v0.y, v1.x, v1.y);
        }
        __syncthreads();   // A2

        // ---- A3: reduce+h (warps 0-7)  |  pv/uv/heads/s2 (warps 8-15) ----
        if (warp < 8) {
            int r = tid >> 2, q = tid & 3;
            float4 s = sm->part4[(q * 4 + 0) * 64 + r];
            #pragma unroll
            for (int j = 1; j < 4; ++j) {
                float4 v = sm->part4[(q * 4 + j) * 64 + r];
                s.x += v.x; s.y += v.y; s.z += v.z; s.w += v.w;
            }
            #pragma unroll
            for (int o = 1; o <= 2; o <<= 1) {
                s.x += __shfl_xor_sync(0xffffffffu, s.x, o);
                s.y += __shfl_xor_sync(0xffffffffu, s.y, o);
                s.z += __shfl_xor_sync(0xffffffffu, s.z, o);
                s.w += __shfl_xor_sync(0xffffffffu, s.w, o);
            }
            if (q == 0) {
                float bb = sm->biasm[r];
                float h0 = fmaxf(s.x + bb, 0.f), h1 = fmaxf(s.y + bb, 0.f);
                float h2 = fmaxf(s.z + bb, 0.f), h3 = fmaxf(s.w + bb, 0.f);
                int R = 64 * rank + r;
                size_t ob = ((size_t)t * BATCH + clus * 4) * HDIM + R;
                out_outputs[ob]           = h0;
                out_outputs[ob + HDIM]    = h1;
                out_outputs[ob + 2*HDIM]  = h2;
                out_outputs[ob + 3*HDIM]  = h3;
                uint32_t off = (uint32_t)((p * 4) * HDIM + R) * 4u;
                #pragma unroll
                for (int d = 0; d < 4; ++d) {
                    stcf(r_hid[d] + off,                 h0);
                    stcf(r_hid[d] + off + HDIM * 4u,     h1);
                    stcf(r_hid[d] + off + 2 * HDIM * 4u, h2);
                    stcf(r_hid[d] + off + 3 * HDIM * 4u, h3);
                }
            }
        } else {
            int wj = warp - 8;
            // pv rows {2wj, 2wj+1} over hid (k 256..511)
            #pragma unroll
            for (int rr2 = 0; rr2 < 2; ++rr2) {
                int rr = 2 * wj + rr2;
                ull a0 = 0, a1 = 0;
                #pragma unroll
                for (int m = 0; m < 8; ++m) {
                    int kk = lane + 32 * m;
                    ull w2 = bcast2(sm->Whs[rr][kk]);
                    a0 = ffma2(w2, sm->xq[0][256 + kk], a0);
                    a1 = ffma2(w2, sm->xq[1][256 + kk], a1);
                }
                a0 = wred2(a0); a1 = wred2(a1);
                if (lane < 4) {
                    float v = fmaxf(pick4(lane, a0, a1) + sm->bhs[rr], 0.f);
                    uint32_t off = (uint32_t)((p * 4 + lane) * SDIM + 16 * rank + rr) * 4u;
                    #pragma unroll
                    for (int d = 0; d < 4; ++d) stcf(r_pv[d] + off, v);
                }
            }
            // uv rows {2wj, 2wj+1} over tops (k 512..639)
            #pragma unroll
            for (int rr2 = 0; rr2 < 2; ++rr2) {
                int rr = 2 * wj + rr2;
                ull a0 = 0, a1 = 0;
                #pragma unroll
                for (int m = 0; m < 4; ++m) {
                    int kk = lane + 32 * m;
                    ull w2 = bcast2(sm->Wsu[rr][kk]);
                    a0 = ffma2(w2, sm->xq[0][512 + kk], a0);
                    a1 = ffma2(w2, sm->xq[1][512 + kk], a1);
                }
                a0 = wred2(a0); a1 = wred2(a1);
                if (lane < 4) {
                    float v = fmaxf(pick4(lane, a0, a1) + sm->bsu[rr], 0.f);
                    uint32_t off = (uint32_t)((p * 4 + lane) * SDIM + 16 * rank + rr) * 4u;
                    #pragma unroll
                    for (int d = 0; d < 4; ++d) stcf(r_uv[d] + off, v);
                }
            }
            // head rows (warps 8-11) for ALL 4 lanes
            if (wj < 4) {
                ull a0 = 0, a1 = 0;
                #pragma unroll
                for (int m = 0; m < 8; ++m) {
                    int kk = lane + 32 * m;
                    ull w2 = bcast2(sm->Whd[wj][kk]);
                    a0 = ffma2(w2, sm->xq[0][256 + kk], a0);
                    a1 = ffma2(w2, sm->xq[1][256 + kk], a1);
                }
                a0 = wred2(a0); a1 = wred2(a1);
                if (lane < 4)
                    sm->lg[lane][wj] = pick4(lane, a0, a1) + sm->bhd[wj];
            }
            // s2 broadcast (warps 14-15): own stack row 2 -> all CTAs
            if (warp >= 14) {
                int d0 = (warp - 14) * 32 + lane;
                float v = sm->stck[sp][2][d0];
                uint32_t off = (uint32_t)((p * 4 + rank) * SDIM + d0) * 4u;
                #pragma unroll
                for (int d = 0; d < 4; ++d) stcf(r_s2[d] + off, v);
            }
        }
        cluster_sync();   // A4 — single cluster sync per step

        // ---- B1: probs (all lanes, local) + x hid/emb rebuild ----
        if (tid < 4) {
            int b = tid;
            float l0 = sm->lg[b][0], l1 = sm->lg[b][1], l2 = sm->lg[b][2];
            float g  = sm->lg[b][3];
            float ssp = (g > 20.f) ? g : log1pf(expf(g));
            float gamma = 1.f + ssp;
            float m = fmaxf(l0, fmaxf(l1, l2));
            float e0 = expf(l0 - m), e1 = expf(l1 - m), e2 = expf(l2 - m);
            float ls = logf(e0 + e1 + e2);
            float s0 = expf(gamma * ((l0 - m) - ls));
            float s1 = expf(gamma * ((l1 - m) - ls));
            float s2 = expf(gamma * ((l2 - m) - ls));
            float inv = 1.f / (s0 + s1 + s2 + 1e-16f);
            sm->pr[b][0] = s0 * inv;
            sm->pr[b][1] = s1 * inv;
            sm->pr[b][2] = s2 * inv;
            if ((uint32_t)b == rank) {
                int idx = 0; float best = s0;
                if (s1 > best) { best = s1; idx = 1; }
                if (s2 > best) idx = 2;
                out_acts[t * BATCH + clus * 4 + rank] = (float)idx;
            }
        }
        #pragma unroll
        for (int j = 0; j < 2; ++j) {
            int e = tid + j * NT;
            int b = e >> 8, k = e & 255;
            float v = sm->hidrx[p][b][k];
            x4f[(256 + k) * 4 + b] = v;
            xqf[((b >> 1) * XQP + 256 + k) * 2 + (b & 1)] = v;
        }
        {
            int b = tid >> 7, k = tid & 127;
            x4f[k * 4 + b]         = pe0;
            x4f[(k + 128) * 4 + b] = pe1;
            xqf[((b >> 1) * XQP + k) * 2 + (b & 1)]       = pe0;
            xqf[((b >> 1) * XQP + k + 128) * 2 + (b & 1)] = pe1;
        }
        __syncthreads();  // B2

        // ---- B3: own stack update | new tops for all lanes ----
        if (tid < 256) {
            int d4 = tid & 15, ic = tid >> 4;
            const float4* Ssrc = (const float4*)sm->stck[sp];
            float4*       Sdst = (float4*)sm->stck[sp ^ 1];
            float pp = sm->pr[rank][0], pq = sm->pr[rank][1], pn = sm->pr[rank][2];
            const float4* pv4 = (const float4*)sm->pvb[p][rank];
            const float4* uv4 = (const float4*)sm->uvb[p][rank];
            #pragma unroll
            for (int ii = 0; ii < 4; ++ii) {
                int i = ic * 4 + ii;
                float4 cur = Ssrc[i * 16 + d4];
                float4 ps  = (i == 0) ? pv4[d4] : Ssrc[(i - 1) * 16 + d4];
                float4 qs;
                if (i == 0)       qs = uv4[d4];
                else if (i < 63)  qs = Ssrc[(i + 1) * 16 + d4];
                else              qs = make_float4(0.f, 0.f, 0.f, 0.f);
                float4 nv;
                nv.x = pp * ps.x + pq * qs.x + pn * cur.x;
                nv.y = pp * ps.y + pq * qs.y + pn * cur.y;
                nv.z = pp * ps.z + pq * qs.z + pn * cur.z;
                nv.w = pp * ps.w + pq * qs.w + pn * cur.w;
                Sdst[i * 16 + d4] = nv;
            }
        } else {
            int e0 = tid - 256;
            #pragma unroll
            for (int j = 0; j < 2; ++j) {
                int e = e0 + j * 256;       // 0..511
                int b = e >> 7, row = (e >> 6) & 1, d = e & 63;
                float pp = sm->pr[b][0], pq = sm->pr[b][1], pn = sm->pr[b][2];
                float old0 = tcf[d * 4 + b];               // old tops row 0
                float nv;
                if (row == 0) {
                    nv = pp * sm->pvb[p][b][d] + pq * sm->uvb[p][b][d] + pn * old0;
                } else {
                    float old1 = tcf[(64 + d) * 4 + b];    // old tops row 1
                    nv = pp * old0 + pq * sm->s2b[p][b][d] + pn * old1;
                }
                int kx = 512 + row * 64 + d;
                x4f[kx * 4 + b] = nv;
                xqf[((b >> 1) * XQP + kx) * 2 + (b & 1)] = nv;
            }
        }
        __syncthreads();  // B6 — x/stacks ready for next step
    }

    // ===================== final outputs =====================
    {
        int bg = clus * 4 + rank;
        if (tid < 256)
            out_hid[bg * HDIM + tid] = x4f[(256 + tid) * 4 + rank];
        // final stack is in stck[0] (t=255: sp=1 -> dst=0)
        for (int e = tid; e < SSZ * SDIM; e += NT)
            out_stack[(size_t)bg * SSZ * SDIM + e] = sm->stck[0][e >> 6][e & 63];
    }
}

extern "C" void kernel_launch(void* const* d_in, const int* in_sizes, int n_in,
                              void* d_out, int out_size) {
    cudaFuncSetAttribute(srnn_kernel,
                         cudaFuncAttributeMaxDynamicSharedMemorySize,
                         (int)sizeof(SM));
    srnn_kernel<<<BATCH, NT, sizeof(SM)>>>(
        (const int*)  d_in[0],
        (const float*)d_in[1],
        (const float*)d_in[2],  (const float*)d_in[3],
        (const float*)d_in[4],  (const float*)d_in[5],
        (const float*)d_in[6],  (const float*)d_in[7],
        (const float*)d_in[8],  (const float*)d_in[9],
        (const float*)d_in[10], (const float*)d_in[11],
        (const float*)d_in[12], (const float*)d_in[13],
        (const float*)d_in[14], (const float*)d_in[15],
        (const float*)d_in[16],
        (float*)d_out);
}

// round 6
// speedup vs baseline: 2.7774x; 1.2533x over previous
#include <cuda_runtime.h>
#include <math.h>
#include <stdint.h>

// EncoderSRNN GB300 R6: unified partial-sum pass (no serial shfl chains),
// x double-buffered by parity, hid DSMEM-written directly into peers' x,
// v4 DSMEM stores, arrive/wait split. 32 clusters x 4 CTAs, 4 lanes/cluster.

#define T_STEPS 256
#define BATCH   128
#define HDIM    256
#define SDIM    64
#define SSZ     64
#define NT      512
#define NKW     40     // k per mhid warp (16*40 = 640)

typedef unsigned long long ull;

struct SM {
    float4 x4[2][640];          // [parity][k] = {b0,b1,b2,b3}   20480 B
    float4 partm[16][65];       // mhid partials (padded)        16640 B
    float4 parts[40][33];       // small-row partials (padded)   21120 B
    float  stck[2][SSZ][SDIM];  // own-lane stack dbl-buf        32768 B
    float  pvb[2][SDIM][4];     // push_val [p][d][b]             2048 B
    float  uvb[2][SDIM][4];     // u_val                          2048 B
    float  s2b[2][4][SDIM];     // old stack row2 [p][b][d]       2048 B
    float  Whs[16][256];        // own 16 pv rows                16384 B
    float  Wsu[16][128];        //                                8192 B
    float  Whd[4][256];         // head rows (W_ha 0-2, W_hg 3)   4096 B
    float  biasm[64];
    float  bhs[16], bsu[16], bhd[4];
    float  lg[4][4];            // [b][head]
    float  pr[4][4];            // [b][push,pop,noop]
};

__device__ __forceinline__ uint32_t s32(const void* p) {
    return (uint32_t)__cvta_generic_to_shared(p);
}
__device__ __forceinline__ uint32_t mapa_r(uint32_t a, uint32_t r) {
    uint32_t ra;
    asm("mapa.shared::cluster.u32 %0, %1, %2;" : "=r"(ra) : "r"(a), "r"(r));
    return ra;
}
__device__ __forceinline__ void stcv4(uint32_t addr, float a, float b, float c, float d) {
    asm volatile("st.shared::cluster.v4.f32 [%0], {%1,%2,%3,%4};"
                 :: "r"(addr), "f"(a), "f"(b), "f"(c), "f"(d) : "memory");
}
__device__ __forceinline__ uint32_t ctarank() {
    uint32_t r; asm("mov.u32 %0, %%cluster_ctarank;" : "=r"(r)); return r;
}
__device__ __forceinline__ ull ffma2(ull a, ull b, ull c) {
    ull d; asm("fma.rn.f32x2 %0, %1, %2, %3;" : "=l"(d) : "l"(a), "l"(b), "l"(c)); return d;
}
__device__ __forceinline__ ull bcast2(float f) {
    ull d; asm("mov.b64 %0, {%1, %1};" : "=l"(d) : "f"(f)); return d;
}
__device__ __forceinline__ float2 unpk(ull v) {
    float2 u; asm("mov.b64 {%0, %1}, %2;" : "=f"(u.x), "=f"(u.y) : "l"(v)); return u;
}
__device__ __forceinline__ float loadW(const float* We, const float* Wh,
                                       const float* Ws, int R, int k) {
    if (k < 256) return We[R * 256 + k];
    if (k < 512) return Wh[R * 256 + (k - 256)];
    return Ws[R * 128 + (k - 512)];
}

template<int NM>
__device__ __forceinline__ void small_partial(const float* Wrow, const ulonglong2* xb,
                                              int koff, int lane, float4* dst) {
    ull a0 = 0, a1 = 0;
    #pragma unroll
    for (int m = 0; m < NM; ++m) {
        int kk = lane + 32 * m;
        ulonglong2 xx = xb[koff + kk];
        ull w = bcast2(Wrow[kk]);
        a0 = ffma2(w, xx.x, a0);
        a1 = ffma2(w, xx.y, a1);
    }
    float2 u0 = unpk(a0), u1 = unpk(a1);
    *dst = make_float4(u0.x, u0.y, u1.x, u1.y);
}

__global__ void __launch_bounds__(NT, 1) __cluster_dims__(4, 1, 1)
srnn_kernel(const int*   __restrict__ inputs,
            const float* __restrict__ emb_W,
            const float* __restrict__ W_hh, const float* __restrict__ b_hh,
            const float* __restrict__ W_eh, const float* __restrict__ b_eh,
            const float* __restrict__ W_ha, const float* __restrict__ b_ha,
            const float* __restrict__ W_hg, const float* __restrict__ b_hg,
            const float* __restrict__ W_hs, const float* __restrict__ b_hs,
            const float* __restrict__ W_sh, const float* __restrict__ b_sh,
            const float* __restrict__ W_su, const float* __restrict__ b_su,
            const float* __restrict__ empty_elem,
            float* __restrict__ out)
{
    extern __shared__ char raw[];
    SM* sm = reinterpret_cast<SM*>(raw);

    const int tid  = threadIdx.x;
    const int warp = tid >> 5;
    const int lane = tid & 31;
    const uint32_t rank = ctarank();
    const int clus = blockIdx.x >> 2;

    float* out_outputs = out;
    float* out_hid     = out + (size_t)T_STEPS * BATCH * HDIM;
    float* out_stack   = out_hid + BATCH * HDIM;
    float* out_acts    = out_stack + (size_t)BATCH * SSZ * SDIM;

    // remote DSMEM bases
    uint32_t r_x4[4], r_pv[4], r_uv[4], r_s2[4];
    #pragma unroll
    for (int d = 0; d < 4; ++d) {
        r_x4[d] = mapa_r(s32(&sm->x4[0][0]),     d);
        r_pv[d] = mapa_r(s32(&sm->pvb[0][0][0]), d);
        r_uv[d] = mapa_r(s32(&sm->uvb[0][0][0]), d);
        r_s2[d] = mapa_r(s32(&sm->s2b[0][0][0]), d);
    }

    // ===================== init =====================
    float wr0[NKW], wr1[NKW];
    {
        int R0 = 64 * (int)rank + lane, R1 = R0 + 32;
        int kb = NKW * warp;
        #pragma unroll
        for (int i = 0; i < NKW; ++i) {
            wr0[i] = loadW(W_eh, W_hh, W_sh, R0, kb + i);
            wr1[i] = loadW(W_eh, W_hh, W_sh, R1, kb + i);
        }
    }
    for (int idx = tid; idx < 16 * 256; idx += NT) {
        int r = idx >> 8, k = idx & 255;
        sm->Whs[r][k] = W_hs[(16 * rank + r) * 256 + k];
    }
    for (int idx = tid; idx < 16 * 128; idx += NT) {
        int r = idx >> 7, k = idx & 127;
        sm->Wsu[r][k] = W_su[(16 * rank + r) * 128 + k];
    }
    for (int idx = tid; idx < 4 * 256; idx += NT) {
        int r = idx >> 8, k = idx & 255;
        sm->Whd[r][k] = (r < 3) ? W_ha[r * 256 + k] : W_hg[k];
    }
    if (tid < 64) {
        int R = 64 * rank + tid;
        sm->biasm[tid] = b_eh[R] + b_hh[R] + b_sh[R];
        if (tid < 16) {
            sm->bhs[tid] = b_hs[16 * rank + tid];
            sm->bsu[tid] = b_su[16 * rank + tid];
        }
        if (tid < 4) sm->bhd[tid] = (tid < 3) ? b_ha[tid] : b_hg[0];
    }
    // x4[0]: emb(t=0) | hid=0 | tops=empty
    for (int e = tid; e < 640 * 4; e += NT) {
        int k = e >> 2, b = e & 3;
        float v;
        if (k < 256) {
            int row = inputs[clus * 4 + b];
            v = emb_W[(size_t)row * 256 + k];
        } else if (k < 512) v = 0.f;
        else                v = empty_elem[(k - 512) & 63];
        ((float*)&sm->x4[0][k])[b] = v;
    }
    for (int e = tid; e < SSZ * SDIM; e += NT)
        sm->stck[0][e >> 6][e & 63] = empty_elem[e & 63];
    asm volatile("barrier.cluster.arrive.aligned;" ::: "memory");
    asm volatile("barrier.cluster.wait.aligned;" ::: "memory");

    // ===================== time loop =====================
    for (int t = 0; t < T_STEPS; ++t) {
        const int p = t & 1;

        // ---------- A1: all partials ----------
        float pe0, pe1;
        {
            int tn = (t + 1 < T_STEPS) ? t + 1 : T_STEPS - 1;
            int b = tid >> 7, k = tid & 127;
            int row = inputs[tn * BATCH + clus * 4 + b];
            pe0 = emb_W[(size_t)row * 256 + k];
            pe1 = emb_W[(size_t)row * 256 + k + 128];
        }
        const ulonglong2* xb = reinterpret_cast<const ulonglong2*>(&sm->x4[p][0]);
        {
            ull a00 = 0, a01 = 0, a10 = 0, a11 = 0;
            const ulonglong2* xv = xb + NKW * warp;
            #pragma unroll
            for (int i = 0; i < NKW; ++i) {
                ulonglong2 xx = xv[i];
                ull w0 = bcast2(wr0[i]);
                a00 = ffma2(w0, xx.x, a00);
                a01 = ffma2(w0, xx.y, a01);
                ull w1 = bcast2(wr1[i]);
                a10 = ffma2(w1, xx.x, a10);
                a11 = ffma2(w1, xx.y, a11);
            }
            float2 u0 = unpk(a00), u1 = unpk(a01);
            sm->partm[warp][lane]      = make_float4(u0.x, u0.y, u1.x, u1.y);
            float2 v0 = unpk(a10), v1 = unpk(a11);
            sm->partm[warp][lane + 32] = make_float4(v0.x, v0.y, v1.x, v1.y);
        }
        small_partial<8>(sm->Whs[warp], xb, 256, lane, &sm->parts[warp][lane]);
        small_partial<4>(sm->Wsu[warp], xb, 512, lane, &sm->parts[16 + warp][lane]);
        if (warp < 4)
            small_partial<8>(sm->Whd[warp], xb, 256, lane, &sm->parts[32 + warp][lane]);
        __syncthreads();

        // ---------- A2: reduce everything + DSMEM broadcast ----------
        if (tid < 256) {
            int r = tid >> 2, q = tid & 3;
            float4 s4 = sm->partm[q * 4][r];
            #pragma unroll
            for (int j = 1; j < 4; ++j) {
                float4 v = sm->partm[q * 4 + j][r];
                s4.x += v.x; s4.y += v.y; s4.z += v.z; s4.w += v.w;
            }
            #pragma unroll
            for (int o = 1; o <= 2; o <<= 1) {
                s4.x += __shfl_xor_sync(0xffffffffu, s4.x, o);
                s4.y += __shfl_xor_sync(0xffffffffu, s4.y, o);
                s4.z += __shfl_xor_sync(0xffffffffu, s4.z, o);
                s4.w += __shfl_xor_sync(0xffffffffu, s4.w, o);
            }
            if (q == 0) {
                float bb = sm->biasm[r];
                float h0 = fmaxf(s4.x + bb, 0.f), h1 = fmaxf(s4.y + bb, 0.f);
                float h2 = fmaxf(s4.z + bb, 0.f), h3 = fmaxf(s4.w + bb, 0.f);
                int R = 64 * rank + r;
                size_t ob = ((size_t)t * BATCH + clus * 4) * HDIM + R;
                out_outputs[ob]            = h0;
                out_outputs[ob + HDIM]     = h1;
                out_outputs[ob + 2 * HDIM] = h2;
                out_outputs[ob + 3 * HDIM] = h3;
                // new hid -> directly into everyone's x4[p^1]
                uint32_t off = (uint32_t)((p ^ 1) * 640 + 256 + R) * 16u;
                #pragma unroll
                for (int d = 0; d < 4; ++d)
                    stcv4(r_x4[d] + off, h0, h1, h2, h3);
            }
        } else if (tid < 416) {            // warps 8-12 fully (shfl-safe)
            int e = tid - 256;
            int vr = e >> 2, s = e & 3;    // vr 0..39 (36-39 dummies)
            float4 acc = make_float4(0.f, 0.f, 0.f, 0.f);
            #pragma unroll
            for (int u = 0; u < 8; ++u) {
                float4 v = sm->parts[vr][s + 4 * u];
                acc.x += v.x; acc.y += v.y; acc.z += v.z; acc.w += v.w;
            }
            #pragma unroll
            for (int o = 1; o <= 2; o <<= 1) {
                acc.x += __shfl_xor_sync(0xffffffffu, acc.x, o);
                acc.y += __shfl_xor_sync(0xffffffffu, acc.y, o);
                acc.z += __shfl_xor_sync(0xffffffffu, acc.z, o);
                acc.w += __shfl_xor_sync(0xffffffffu, acc.w, o);
            }
            if (s == 0 && vr < 36) {
                if (vr < 16) {
                    float bb = sm->bhs[vr];
                    int dd = 16 * (int)rank + vr;
                    uint32_t off = (uint32_t)(p * 64 + dd) * 16u;
                    #pragma unroll
                    for (int d = 0; d < 4; ++d)
                        stcv4(r_pv[d] + off,
                              fmaxf(acc.x + bb, 0.f), fmaxf(acc.y + bb, 0.f),
                              fmaxf(acc.z + bb, 0.f), fmaxf(acc.w + bb, 0.f));
                } else if (vr < 32) {
                    float bb = sm->bsu[vr - 16];
                    int dd = 16 * (int)rank + (vr - 16);
                    uint32_t off = (uint32_t)(p * 64 + dd) * 16u;
                    #pragma unroll
                    for (int d = 0; d < 4; ++d)
                        stcv4(r_uv[d] + off,
                              fmaxf(acc.x + bb, 0.f), fmaxf(acc.y + bb, 0.f),
                              fmaxf(acc.z + bb, 0.f), fmaxf(acc.w + bb, 0.f));
                } else {
                    int h = vr - 32;
                    float bb = sm->bhd[h];
                    sm->lg[0][h] = acc.x + bb;
                    sm->lg[1][h] = acc.y + bb;
                    sm->lg[2][h] = acc.z + bb;
                    sm->lg[3][h] = acc.w + bb;
                }
            }
        } else if (tid < 432) {            // s2 broadcast (own stack row 2)
            int t2 = tid - 416;
            const float4* s2src = reinterpret_cast<const float4*>(&sm->stck[p][2][0]);
            float4 v = s2src[t2];
            uint32_t off = (uint32_t)((p * 4 + rank) * 64 + 4 * t2) * 4u;
            #pragma unroll
            for (int d = 0; d < 4; ++d)
                stcv4(r_s2[d] + off, v.x, v.y, v.z, v.w);
        }
        __syncthreads();
        asm volatile("barrier.cluster.arrive.aligned;" ::: "memory");

        // ---------- local-only work while peers catch up ----------
        if (tid < 4) {
            int b = tid;
            float l0 = sm->lg[b][0], l1 = sm->lg[b][1], l2 = sm->lg[b][2];
            float g  = sm->lg[b][3];
            float ssp = (g > 20.f) ? g : log1pf(expf(g));
            float gamma = 1.f + ssp;
            float m = fmaxf(l0, fmaxf(l1, l2));
            float e0 = expf(l0 - m), e1 = expf(l1 - m), e2 = expf(l2 - m);
            float ls = logf(e0 + e1 + e2);
            float s0 = expf(gamma * ((l0 - m) - ls));
            float s1 = expf(gamma * ((l1 - m) - ls));
            float s2 = expf(gamma * ((l2 - m) - ls));
            float inv = 1.f / (s0 + s1 + s2 + 1e-16f);
            sm->pr[b][0] = s0 * inv;
            sm->pr[b][1] = s1 * inv;
            sm->pr[b][2] = s2 * inv;
            if ((uint32_t)b == rank) {
                int idx = 0; float best = s0;
                if (s1 > best) { best = s1; idx = 1; }
                if (s2 > best) idx = 2;
                out_acts[t * BATCH + clus * 4 + rank] = (float)idx;
            }
        }
        {   // emb for next step into x4[p^1]
            int b = tid >> 7, k = tid & 127;
            float* dst = (float*)&sm->x4[p ^ 1][0];
            dst[k * 4 + b]         = pe0;
            dst[(k + 128) * 4 + b] = pe1;
        }
        asm volatile("barrier.cluster.wait.aligned;" ::: "memory");
        __syncthreads();

        // ---------- B: stack update + new tops ----------
        if (tid < 256) {
            int d4 = tid & 15, ic = tid >> 4;
            const float4* Ssrc = (const float4*)sm->stck[p];
            float4*       Sdst = (float4*)sm->stck[p ^ 1];
            float pp = sm->pr[rank][0], pq = sm->pr[rank][1], pn = sm->pr[rank][2];
            float4 pv4 = make_float4(sm->pvb[p][d4 * 4 + 0][rank],
                                     sm->pvb[p][d4 * 4 + 1][rank],
                                     sm->pvb[p][d4 * 4 + 2][rank],
                                     sm->pvb[p][d4 * 4 + 3][rank]);
            float4 uv4 = make_float4(sm->uvb[p][d4 * 4 + 0][rank],
                                     sm->uvb[p][d4 * 4 + 1][rank],
                                     sm->uvb[p][d4 * 4 + 2][rank],
                                     sm->uvb[p][d4 * 4 + 3][rank]);
            #pragma unroll
            for (int ii = 0; ii < 4; ++ii) {
                int i = ic * 4 + ii;
                float4 cur = Ssrc[i * 16 + d4];
                float4 ps  = (i == 0) ? pv4 : Ssrc[(i - 1) * 16 + d4];
                float4 qs;
                if (i == 0)      qs = uv4;
                else if (i < 63) qs = Ssrc[(i + 1) * 16 + d4];
                else             qs = make_float4(0.f, 0.f, 0.f, 0.f);
                float4 nv;
                nv.x = pp * ps.x + pq * qs.x + pn * cur.x;
                nv.y = pp * ps.y + pq * qs.y + pn * cur.y;
                nv.z = pp * ps.z + pq * qs.z + pn * cur.z;
                nv.w = pp * ps.w + pq * qs.w + pn * cur.w;
                Sdst[i * 16 + d4] = nv;
            }
        } else {
            int e0 = tid - 256;
            #pragma unroll
            for (int j = 0; j < 2; ++j) {
                int e = e0 + j * 256;
                int b = e >> 7, row = (e >> 6) & 1, d = e & 63;
                float pp = sm->pr[b][0], pq = sm->pr[b][1], pn = sm->pr[b][2];
                float old0 = ((float*)&sm->x4[p][512 + d])[b];
                float nv;
                if (row == 0) {
                    nv = pp * sm->pvb[p][d][b] + pq * sm->uvb[p][d][b] + pn * old0;
                } else {
                    float old1 = ((float*)&sm->x4[p][576 + d])[b];
                    nv = pp * old0 + pq * sm->s2b[p][b][d] + pn * old1;
                }
                ((float*)&sm->x4[p ^ 1][512 + row * 64 + d])[b] = nv;
            }
        }
        __syncthreads();
    }

    // ===================== final outputs =====================
    {
        int bg = clus * 4 + rank;
        if (tid < 256)
            out_hid[bg * HDIM + tid] = ((float*)&sm->x4[0][256 + tid])[rank];
        for (int e = tid; e < SSZ * SDIM; e += NT)
            out_stack[(size_t)bg * SSZ * SDIM + e] = sm->stck[0][e >> 6][e & 63];
    }
}

extern "C" void kernel_launch(void* const* d_in, const int* in_sizes, int n_in,
                              void* d_out, int out_size) {
    cudaFuncSetAttribute(srnn_kernel,
                         cudaFuncAttributeMaxDynamicSharedMemorySize,
                         (int)sizeof(SM));
    srnn_kernel<<<BATCH, NT, sizeof(SM)>>>(
        (const int*)  d_in[0],
        (const float*)d_in[1],
        (const float*)d_in[2],  (const float*)d_in[3],
        (const float*)d_in[4],  (const float*)d_in[5],
        (const float*)d_in[6],  (const float*)d_in[7],
        (const float*)d_in[8],  (const float*)d_in[9],
        (const float*)d_in[10], (const float*)d_in[11],
        (const float*)d_in[12], (const float*)d_in[13],
        (const float*)d_in[14], (const float*)d_in[15],
        (const float*)d_in[16],
        (float*)d_out);
}